// round 16
// baseline (speedup 1.0000x reference)
#include <cuda_runtime.h>
#include <cuda_bf16.h>
#include <cstdint>

// MHA B=4096,T=128,C=128,H=4,D=32 causal, scale=C^-0.5
// Warp-level mma.sync (bf16, fp32 accum) with hi/lo split precision.
// R15: 1024 threads = 32 warps (8x4 warp grid), per-warp m-tile 16 -> occ 2x.

#define NB 4096
#define SCALE 0.08838834764831845f

// smem row strides (bytes)
#define S128 272   // 128 bf16 rows (256B) + 16 pad
#define SW   208   // 96 bf16 rows (192B) + 16 pad
#define S32  80    // 32 bf16 rows (64B) + 16 pad

// smem byte offsets
#define O_XH   0                  // x hi  [128 t][128 c] bf16, stride S128
#define O_XL   34816
#define O_PH   69632              // P hi [128 t][128 s]  (union with WB)
#define O_PL   104448
#define O_WBH  69632              // W hi [128 c][96 n] stride SW (n = m*32+d)
#define O_WBL  96256
#define O_QT   139264             // Q bf16 [128 t][32 d] stride S32 (pre-scaled)
#define O_KT   149504             // K bf16 [128 s][32 d]
#define O_VH   159744             // V hi [128 s][32 d]
#define O_VL   169984
#define O_OH   180224             // O hi [128 t][32 d]
#define O_OL   190464
#define O_WPH  200704             // Wp hi [128 c][32 d]
#define O_WPL  210944
#define O_RED  221184             // float [4 wc][2][128]
#define SMEM_BYTES 225280

__device__ __forceinline__ uint32_t cvta_s(const void* p) {
    uint32_t a;
    asm("{ .reg .u64 t; cvta.to.shared.u64 t, %1; cvt.u32.u64 %0, t; }" : "=r"(a) : "l"(p));
    return a;
}
__device__ __forceinline__ void ldsm4(uint32_t* r, uint32_t a) {
    asm volatile("ldmatrix.sync.aligned.m8n8.x4.shared.b16 {%0,%1,%2,%3}, [%4];"
                 : "=r"(r[0]), "=r"(r[1]), "=r"(r[2]), "=r"(r[3]) : "r"(a));
}
__device__ __forceinline__ void ldsm2t(uint32_t* r, uint32_t a) {
    asm volatile("ldmatrix.sync.aligned.m8n8.x2.trans.shared.b16 {%0,%1}, [%2];"
                 : "=r"(r[0]), "=r"(r[1]) : "r"(a));
}
__device__ __forceinline__ void ldsm4t(uint32_t* r, uint32_t a) {
    asm volatile("ldmatrix.sync.aligned.m8n8.x4.trans.shared.b16 {%0,%1,%2,%3}, [%4];"
                 : "=r"(r[0]), "=r"(r[1]), "=r"(r[2]), "=r"(r[3]) : "r"(a));
}
__device__ __forceinline__ void mma16816(float* c, const uint32_t* a, const uint32_t* b) {
    asm volatile("mma.sync.aligned.m16n8k16.row.col.f32.bf16.bf16.f32 "
                 "{%0,%1,%2,%3}, {%4,%5,%6,%7}, {%8,%9}, {%0,%1,%2,%3};"
                 : "+f"(c[0]), "+f"(c[1]), "+f"(c[2]), "+f"(c[3])
                 : "r"(a[0]), "r"(a[1]), "r"(a[2]), "r"(a[3]), "r"(b[0]), "r"(b[1]));
}
__device__ __forceinline__ uint32_t packbf(float lo, float hi) {
    uint32_t d;
    asm("cvt.rn.bf16x2.f32 %0, %1, %2;" : "=r"(d) : "f"(hi), "f"(lo));
    return d;
}
__device__ __forceinline__ void split2(float v, float& h, float& l) {
    __nv_bfloat16 hb = __float2bfloat16(v);
    h = __bfloat162float(hb);
    l = v - h;
}
__device__ __forceinline__ void st_split2(char* sm_, uint32_t hiOff, uint32_t loOff,
                                          uint32_t boff, float v0, float v1) {
    float h0, l0, h1, l1;
    split2(v0, h0, l0); split2(v1, h1, l1);
    *reinterpret_cast<uint32_t*>(sm_ + hiOff + boff) = packbf(h0, h1);
    *reinterpret_cast<uint32_t*>(sm_ + loOff + boff) = packbf(l0, l1);
}

__global__ void __launch_bounds__(1024, 1)
mha_mma_kernel(const float* __restrict__ x,
               const float* __restrict__ Wq,
               const float* __restrict__ Wk,
               const float* __restrict__ Wv,
               const float* __restrict__ Wp,
               const float* __restrict__ bp,
               float* __restrict__ out)
{
    extern __shared__ char sm[];
    const uint32_t sb = cvta_s(sm);
    const int tid  = threadIdx.x;
    const int lane = tid & 31;
    const int warp = tid >> 5;
    const int wr   = warp >> 2;      // warp row group 0..7 (m0 = wr*16)
    const int wc   = warp & 3;       // warp col group 0..3
    const int g    = lane >> 2;      // fragment row within 8
    const int qj   = lane & 3;       // fragment col quad
    const int b    = blockIdx.x;
    const int m0   = wr * 16;

    // ---- stage x -> XH/XL (u32 stores) ----
    {
        int t = tid >> 3, q8 = tid & 7;
        const float* xr = x + ((size_t)b * 128 + t) * 128;
        uint32_t base = (uint32_t)t * S128;
        #pragma unroll
        for (int i = 0; i < 8; ++i) {
            int c = 2 * q8 + 16 * i;
            float2 v = *reinterpret_cast<const float2*>(xr + c);
            st_split2(sm, O_XH, O_XL, base + c * 2, v.x, v.y);
        }
    }

    float oacc[4][4];   // persistent out fragments (1 mt x 4 nt)
    #pragma unroll
    for (int f = 0; f < 4; ++f)
        #pragma unroll
        for (int r = 0; r < 4; ++r) oacc[f][r] = 0.f;

    for (int h = 0; h < 4; ++h) {
        // ---- stage W [c][n] (n=m*32+d) and Wp slice [c][d] ----
        {
            int c = tid >> 3, q8 = tid & 7;
            #pragma unroll
            for (int m = 0; m < 3; ++m) {
                const float* w = ((m == 0) ? Wq : (m == 1) ? Wk : Wv)
                                 + ((size_t)h * 128 + c) * 32;
                uint32_t base = (uint32_t)c * SW + m * 64;
                #pragma unroll
                for (int i = 0; i < 2; ++i) {
                    int d = 2 * q8 + 16 * i;
                    float2 v = *reinterpret_cast<const float2*>(w + d);
                    st_split2(sm, O_WBH, O_WBL, base + d * 2, v.x, v.y);
                }
            }
            const float* wp = Wp + (size_t)c * 128 + h * 32;
            uint32_t base = (uint32_t)c * S32;
            #pragma unroll
            for (int i = 0; i < 2; ++i) {
                int d = 2 * q8 + 16 * i;
                float2 v = *reinterpret_cast<const float2*>(wp + d);
                st_split2(sm, O_WPH, O_WPL, base + d * 2, v.x, v.y);
            }
        }
        __syncthreads();

        // ---- G1: QKV[t][n] = sum_c x[t][c]*W[c][n]  M16/warp N96 K128, 3-pass ----
        {
            const int n0 = wc * 24;
            float acc[3][4];
            #pragma unroll
            for (int f = 0; f < 3; ++f)
                #pragma unroll
                for (int r = 0; r < 4; ++r) acc[f][r] = 0.f;

            const uint32_t aAh = sb + O_XH + (m0 + (lane & 15)) * S128 + ((lane >> 4) * 8) * 2;
            const uint32_t aAl = sb + O_XL + (m0 + (lane & 15)) * S128 + ((lane >> 4) * 8) * 2;
            const uint32_t aB4 = (uint32_t)(lane & 15) * SW + (n0 + (lane >> 4) * 8) * 2;
            const uint32_t aB2 = (uint32_t)(lane & 15) * SW + (n0 + 16) * 2;

            #pragma unroll
            for (int k = 0; k < 128; k += 16) {
                uint32_t ah[4], al[4], bh[3][2], bl[3][2];
                ldsm4(ah, aAh + k * 2);
                ldsm4(al, aAl + k * 2);
                ldsm4t(&bh[0][0], sb + O_WBH + aB4 + k * SW);   // nt0,nt1
                ldsm2t(bh[2],     sb + O_WBH + aB2 + k * SW);   // nt2
                ldsm4t(&bl[0][0], sb + O_WBL + aB4 + k * SW);
                ldsm2t(bl[2],     sb + O_WBL + aB2 + k * SW);
                #pragma unroll
                for (int nt = 0; nt < 3; ++nt) {
                    mma16816(acc[nt], ah, bh[nt]);
                    mma16816(acc[nt], ah, bl[nt]);
                    mma16816(acc[nt], al, bh[nt]);
                }
            }
            // epilogue: Q (scaled bf16), K (bf16), V (hi/lo) — u32-packed
            #pragma unroll
            for (int nt = 0; nt < 3; ++nt) {
                int nb = n0 + nt * 8;
                #pragma unroll
                for (int hf = 0; hf < 2; ++hf) {
                    int t = m0 + hf * 8 + g;
                    float v0 = acc[nt][hf * 2 + 0];
                    float v1 = acc[nt][hf * 2 + 1];
                    int n = nb + qj * 2;
                    if (nb < 32) {
                        *reinterpret_cast<uint32_t*>(sm + O_QT + t * S32 + n * 2)
                            = packbf(v0 * SCALE, v1 * SCALE);
                    } else if (nb < 64) {
                        *reinterpret_cast<uint32_t*>(sm + O_KT + t * S32 + (n - 32) * 2)
                            = packbf(v0, v1);
                    } else {
                        st_split2(sm, O_VH, O_VL, (uint32_t)(t * S32 + (n - 64) * 2), v0, v1);
                    }
                }
            }
        }
        __syncthreads();

        // ---- G2: S = Q K^T (M16/warp N128 K32) + causal softmax ----
        {
            const int n0 = wc * 32;
            const bool dead = (2 * wc > wr);   // tile fully above diagonal
            float* red = reinterpret_cast<float*>(sm + O_RED);
            float sc[4][4];
            float mloc[2], fac[2];

            if (!dead) {
                #pragma unroll
                for (int f = 0; f < 4; ++f)
                    #pragma unroll
                    for (int r = 0; r < 4; ++r) sc[f][r] = 0.f;

                const uint32_t aA  = sb + O_QT + (m0 + (lane & 15)) * S32 + ((lane >> 4) * 8) * 2;
                const uint32_t aB4 = sb + O_KT
                    + (n0 + (lane >> 4) * 8 + (lane & 7)) * S32 + (((lane >> 3) & 1) * 8) * 2;
                #pragma unroll
                for (int k = 0; k < 32; k += 16) {
                    uint32_t qa[4], kb[4][2];
                    ldsm4(qa, aA + k * 2);
                    ldsm4(&kb[0][0], aB4 + k * 2);              // nt0,nt1
                    ldsm4(&kb[2][0], aB4 + 16 * S32 + k * 2);   // nt2,nt3
                    #pragma unroll
                    for (int nt = 0; nt < 4; ++nt)
                        mma16816(sc[nt], qa, kb[nt]);
                }

                #pragma unroll
                for (int hf = 0; hf < 2; ++hf) {
                    int t = m0 + hf * 8 + g;
                    float mx = -3.0e38f;
                    #pragma unroll
                    for (int nt = 0; nt < 4; ++nt)
                        #pragma unroll
                        for (int j = 0; j < 2; ++j) {
                            int s = n0 + nt * 8 + qj * 2 + j;
                            float v = sc[nt][hf * 2 + j];
                            if (s <= t) mx = fmaxf(mx, v);
                            else sc[nt][hf * 2 + j] = -3.0e38f;
                        }
                    mx = fmaxf(mx, __shfl_xor_sync(0xffffffffu, mx, 1));
                    mx = fmaxf(mx, __shfl_xor_sync(0xffffffffu, mx, 2));
                    float s = 0.f;
                    #pragma unroll
                    for (int nt = 0; nt < 4; ++nt)
                        #pragma unroll
                        for (int j = 0; j < 2; ++j) {
                            float v = sc[nt][hf * 2 + j];
                            float e = (v > -1.0e38f) ? __expf(v - mx) : 0.f;
                            sc[nt][hf * 2 + j] = e;
                            s += e;
                        }
                    s += __shfl_xor_sync(0xffffffffu, s, 1);
                    s += __shfl_xor_sync(0xffffffffu, s, 2);
                    mloc[hf] = mx;
                    if (qj == 0) {
                        red[(wc * 2 + 0) * 128 + t] = mx;
                        red[(wc * 2 + 1) * 128 + t] = s;
                    }
                }
            } else if (qj == 0) {
                #pragma unroll
                for (int hf = 0; hf < 2; ++hf) {
                    int t = m0 + hf * 8 + g;
                    red[(wc * 2 + 0) * 128 + t] = -3.0e38f;
                    red[(wc * 2 + 1) * 128 + t] = 0.f;
                }
            }
            __syncthreads();

            if (!dead) {
                #pragma unroll
                for (int hf = 0; hf < 2; ++hf) {
                    int t = m0 + hf * 8 + g;
                    float m = -3.0e38f;
                    #pragma unroll
                    for (int w4 = 0; w4 < 4; ++w4) m = fmaxf(m, red[(w4 * 2) * 128 + t]);
                    float sum = 0.f;
                    #pragma unroll
                    for (int w4 = 0; w4 < 4; ++w4)
                        sum += red[(w4 * 2 + 1) * 128 + t] * __expf(red[(w4 * 2) * 128 + t] - m);
                    fac[hf] = __expf(mloc[hf] - m) / sum;
                }
                #pragma unroll
                for (int hf = 0; hf < 2; ++hf) {
                    int t = m0 + hf * 8 + g;
                    #pragma unroll
                    for (int nt = 0; nt < 4; ++nt) {
                        int s0 = n0 + nt * 8 + qj * 2;
                        st_split2(sm, O_PH, O_PL, (uint32_t)(t * S128 + s0 * 2),
                                  sc[nt][hf * 2 + 0] * fac[hf],
                                  sc[nt][hf * 2 + 1] * fac[hf]);
                    }
                }
            }
        }
        __syncthreads();

        // ---- G3: O = P V (M16/warp N32, causal-bounded K, trans-B x4 from V[s][d]) ----
        {
            const int n0 = wc * 8;
            float oc[4];
            #pragma unroll
            for (int r = 0; r < 4; ++r) oc[r] = 0.f;

            const uint32_t aPh = sb + O_PH + (m0 + (lane & 15)) * S128 + ((lane >> 4) * 8) * 2;
            const uint32_t aPl = sb + O_PL + (m0 + (lane & 15)) * S128 + ((lane >> 4) * 8) * 2;
            const uint32_t aVt = (uint32_t)lane * S32 + n0 * 2;   // 32 rows s per x4t
            const int kend = (wr + 1) * 16;                       // P[t][s]=0 for s>t
            uint32_t vh[4], vl[4];
            for (int k = 0; k < kend; k += 16) {
                if ((k & 31) == 0) {
                    ldsm4t(vh, sb + O_VH + aVt + k * S32);
                    ldsm4t(vl, sb + O_VL + aVt + k * S32);
                }
                const uint32_t* vhp = vh + 2 * ((k >> 4) & 1);
                const uint32_t* vlp = vl + 2 * ((k >> 4) & 1);
                uint32_t ph[4], pl[4];
                ldsm4(ph, aPh + k * 2);
                ldsm4(pl, aPl + k * 2);
                mma16816(oc, ph, vhp);
                mma16816(oc, ph, vlp);
                mma16816(oc, pl, vhp);
            }
            #pragma unroll
            for (int hf = 0; hf < 2; ++hf) {
                int t = m0 + hf * 8 + g;
                int d0 = n0 + qj * 2;
                st_split2(sm, O_OH, O_OL, (uint32_t)(t * S32 + d0 * 2),
                          oc[hf * 2 + 0], oc[hf * 2 + 1]);
            }
        }
        __syncthreads();

        // ---- G4: OUT += O Wp^T (M16/warp N128 K32, 3-pass, reg-persistent) ----
        {
            const int n0 = wc * 32;
            const uint32_t aOh = sb + O_OH + (m0 + (lane & 15)) * S32 + ((lane >> 4) * 8) * 2;
            const uint32_t aOl = sb + O_OL + (m0 + (lane & 15)) * S32 + ((lane >> 4) * 8) * 2;
            const uint32_t aW4 = (uint32_t)(n0 + (lane >> 4) * 8 + (lane & 7)) * S32
                                 + (((lane >> 3) & 1) * 8) * 2;
            #pragma unroll
            for (int k = 0; k < 32; k += 16) {
                uint32_t oh[4], ol[4], wh[4][2], wl[4][2];
                ldsm4(oh, aOh + k * 2);
                ldsm4(ol, aOl + k * 2);
                ldsm4(&wh[0][0], sb + O_WPH + aW4 + k * 2);
                ldsm4(&wh[2][0], sb + O_WPH + aW4 + 16 * S32 + k * 2);
                ldsm4(&wl[0][0], sb + O_WPL + aW4 + k * 2);
                ldsm4(&wl[2][0], sb + O_WPL + aW4 + 16 * S32 + k * 2);
                #pragma unroll
                for (int nt = 0; nt < 4; ++nt) {
                    mma16816(oacc[nt], oh, wh[nt]);
                    mma16816(oacc[nt], oh, wl[nt]);
                    mma16816(oacc[nt], ol, wh[nt]);
                }
            }
        }
        __syncthreads();   // next head's staging overwrites W/Wp regions
    }

    // ---- final store: out = oacc + bp ----
    {
        const int n0 = wc * 32;
        #pragma unroll
        for (int nt = 0; nt < 4; ++nt) {
            int c = n0 + nt * 8 + qj * 2;
            float2 bv = *reinterpret_cast<const float2*>(bp + c);
            #pragma unroll
            for (int hf = 0; hf < 2; ++hf) {
                int t = m0 + hf * 8 + g;
                float2 v;
                v.x = oacc[nt][hf * 2 + 0] + bv.x;
                v.y = oacc[nt][hf * 2 + 1] + bv.y;
                *reinterpret_cast<float2*>(out + ((size_t)b * 128 + t) * 128 + c) = v;
            }
        }
    }
}

extern "C" void kernel_launch(void* const* d_in, const int* in_sizes, int n_in,
                              void* d_out, int out_size)
{
    (void)in_sizes; (void)n_in; (void)out_size;
    const float* x  = (const float*)d_in[0];
    const float* Wq = (const float*)d_in[1];
    const float* Wk = (const float*)d_in[2];
    const float* Wv = (const float*)d_in[3];
    const float* Wp = (const float*)d_in[4];
    const float* bp = (const float*)d_in[5];
    float* out = (float*)d_out;

    cudaFuncSetAttribute(mha_mma_kernel,
                         cudaFuncAttributeMaxDynamicSharedMemorySize, SMEM_BYTES);
    mha_mma_kernel<<<NB, 1024, SMEM_BYTES>>>(x, Wq, Wk, Wv, Wp, bp, out);
}

// round 17
// speedup vs baseline: 1.2989x; 1.2989x over previous
#include <cuda_runtime.h>
#include <cuda_bf16.h>
#include <cstdint>

// MHA B=4096,T=128,C=128,H=4,D=32 causal, scale=C^-0.5
// Warp-level mma.sync, 512 threads = 16 warps (4x4 warp grid).
// R16: back to 512-thread R13 layout; G1 stays bf16 hi/lo 3-pass;
//      G3 (P·V) and G4 (O·Wp) switch to fp16 single-pass (P,V,O,Wp fp16).

#define NB 4096
#define SCALE 0.08838834764831845f

// smem row strides (bytes)
#define S128 272   // 128 bf16 rows (256B) + 16 pad
#define SW   208   // 96 bf16 rows (192B) + 16 pad
#define S32  80    // 32 bf16 rows (64B) + 16 pad

// smem byte offsets
#define O_XH   0                  // x hi  [128 t][128 c] bf16, stride S128
#define O_XL   34816
#define O_WBH  69632              // W hi [128 c][96 n] stride SW (union with PF)
#define O_WBL  96256
#define O_PF   69632              // P fp16 [128 t][128 s] stride S128
#define O_QT   122880             // Q bf16 [128 t][32 d] stride S32 (pre-scaled)
#define O_KT   133120             // K bf16 [128 s][32 d]
#define O_VF   143360             // V fp16 [128 s][32 d]
#define O_OF   153600             // O fp16 [128 t][32 d]
#define O_WPF  163840             // Wp fp16 [128 c][32 d]
#define O_RED  174080             // float [4 wc][2][128]
#define SMEM_BYTES 178176

__device__ __forceinline__ uint32_t cvta_s(const void* p) {
    uint32_t a;
    asm("{ .reg .u64 t; cvta.to.shared.u64 t, %1; cvt.u32.u64 %0, t; }" : "=r"(a) : "l"(p));
    return a;
}
__device__ __forceinline__ void ldsm4(uint32_t* r, uint32_t a) {
    asm volatile("ldmatrix.sync.aligned.m8n8.x4.shared.b16 {%0,%1,%2,%3}, [%4];"
                 : "=r"(r[0]), "=r"(r[1]), "=r"(r[2]), "=r"(r[3]) : "r"(a));
}
__device__ __forceinline__ void ldsm2t(uint32_t* r, uint32_t a) {
    asm volatile("ldmatrix.sync.aligned.m8n8.x2.trans.shared.b16 {%0,%1}, [%2];"
                 : "=r"(r[0]), "=r"(r[1]) : "r"(a));
}
__device__ __forceinline__ void ldsm4t(uint32_t* r, uint32_t a) {
    asm volatile("ldmatrix.sync.aligned.m8n8.x4.trans.shared.b16 {%0,%1,%2,%3}, [%4];"
                 : "=r"(r[0]), "=r"(r[1]), "=r"(r[2]), "=r"(r[3]) : "r"(a));
}
__device__ __forceinline__ void mma16816(float* c, const uint32_t* a, const uint32_t* b) {
    asm volatile("mma.sync.aligned.m16n8k16.row.col.f32.bf16.bf16.f32 "
                 "{%0,%1,%2,%3}, {%4,%5,%6,%7}, {%8,%9}, {%0,%1,%2,%3};"
                 : "+f"(c[0]), "+f"(c[1]), "+f"(c[2]), "+f"(c[3])
                 : "r"(a[0]), "r"(a[1]), "r"(a[2]), "r"(a[3]), "r"(b[0]), "r"(b[1]));
}
__device__ __forceinline__ void mma16816h(float* c, const uint32_t* a, const uint32_t* b) {
    asm volatile("mma.sync.aligned.m16n8k16.row.col.f32.f16.f16.f32 "
                 "{%0,%1,%2,%3}, {%4,%5,%6,%7}, {%8,%9}, {%0,%1,%2,%3};"
                 : "+f"(c[0]), "+f"(c[1]), "+f"(c[2]), "+f"(c[3])
                 : "r"(a[0]), "r"(a[1]), "r"(a[2]), "r"(a[3]), "r"(b[0]), "r"(b[1]));
}
__device__ __forceinline__ uint32_t packbf(float lo, float hi) {
    uint32_t d;
    asm("cvt.rn.bf16x2.f32 %0, %1, %2;" : "=r"(d) : "f"(hi), "f"(lo));
    return d;
}
__device__ __forceinline__ uint32_t packh(float lo, float hi) {
    uint32_t d;
    asm("cvt.rn.f16x2.f32 %0, %1, %2;" : "=r"(d) : "f"(hi), "f"(lo));
    return d;
}
__device__ __forceinline__ void split2(float v, float& h, float& l) {
    __nv_bfloat16 hb = __float2bfloat16(v);
    h = __bfloat162float(hb);
    l = v - h;
}
__device__ __forceinline__ void st_split2(char* sm_, uint32_t hiOff, uint32_t loOff,
                                          uint32_t boff, float v0, float v1) {
    float h0, l0, h1, l1;
    split2(v0, h0, l0); split2(v1, h1, l1);
    *reinterpret_cast<uint32_t*>(sm_ + hiOff + boff) = packbf(h0, h1);
    *reinterpret_cast<uint32_t*>(sm_ + loOff + boff) = packbf(l0, l1);
}

__global__ void __launch_bounds__(512, 1)
mha_mma_kernel(const float* __restrict__ x,
               const float* __restrict__ Wq,
               const float* __restrict__ Wk,
               const float* __restrict__ Wv,
               const float* __restrict__ Wp,
               const float* __restrict__ bp,
               float* __restrict__ out)
{
    extern __shared__ char sm[];
    const uint32_t sb = cvta_s(sm);
    const int tid  = threadIdx.x;
    const int lane = tid & 31;
    const int warp = tid >> 5;
    const int wr   = warp >> 2;      // warp row group (m0 = wr*32)
    const int wc   = warp & 3;       // warp col group
    const int g    = lane >> 2;      // fragment row within 8
    const int qj   = lane & 3;       // fragment col quad
    const int b    = blockIdx.x;

    // ---- stage x -> XH/XL (conflict-free u32 stores) ----
    {
        int t = tid >> 2, q4 = tid & 3;
        const float* xr = x + ((size_t)b * 128 + t) * 128;
        uint32_t base = (uint32_t)t * S128;
        #pragma unroll
        for (int i = 0; i < 16; ++i) {
            int c = 2 * q4 + 8 * i;
            float2 v = *reinterpret_cast<const float2*>(xr + c);
            st_split2(sm, O_XH, O_XL, base + c * 2, v.x, v.y);
        }
    }

    float oacc[8][4];   // persistent out fragments (2 mt x 4 nt)
    #pragma unroll
    for (int f = 0; f < 8; ++f)
        #pragma unroll
        for (int r = 0; r < 4; ++r) oacc[f][r] = 0.f;

    for (int h = 0; h < 4; ++h) {
        // ---- stage W [c][n] (n=m*32+d, bf16 hi/lo) and Wp slice [c][d] (fp16) ----
        {
            int c = tid >> 2, q4 = tid & 3;
            #pragma unroll
            for (int m = 0; m < 3; ++m) {
                const float* w = ((m == 0) ? Wq : (m == 1) ? Wk : Wv)
                                 + ((size_t)h * 128 + c) * 32;
                uint32_t base = (uint32_t)c * SW + m * 64;
                #pragma unroll
                for (int i = 0; i < 4; ++i) {
                    int d = 2 * q4 + 8 * i;
                    float2 v = *reinterpret_cast<const float2*>(w + d);
                    st_split2(sm, O_WBH, O_WBL, base + d * 2, v.x, v.y);
                }
            }
            const float* wp = Wp + (size_t)c * 128 + h * 32;
            uint32_t base = (uint32_t)c * S32;
            #pragma unroll
            for (int i = 0; i < 4; ++i) {
                int d = 2 * q4 + 8 * i;
                float2 v = *reinterpret_cast<const float2*>(wp + d);
                *reinterpret_cast<uint32_t*>(sm + O_WPF + base + d * 2) = packh(v.x, v.y);
            }
        }
        __syncthreads();

        // ---- G1: QKV[t][n] = sum_c x[t][c]*W[c][n]  M128 N96 K128, split 3-pass ----
        {
            const int m0 = wr * 32, n0 = wc * 24;
            float acc[6][4];
            #pragma unroll
            for (int f = 0; f < 6; ++f)
                #pragma unroll
                for (int r = 0; r < 4; ++r) acc[f][r] = 0.f;

            const uint32_t aAh = sb + O_XH + (m0 + (lane & 15)) * S128 + ((lane >> 4) * 8) * 2;
            const uint32_t aAl = sb + O_XL + (m0 + (lane & 15)) * S128 + ((lane >> 4) * 8) * 2;
            const uint32_t aB4 = (uint32_t)(lane & 15) * SW + (n0 + (lane >> 4) * 8) * 2;
            const uint32_t aB2 = (uint32_t)(lane & 15) * SW + (n0 + 16) * 2;

            #pragma unroll
            for (int k = 0; k < 128; k += 16) {
                uint32_t ah[2][4], al[2][4], bh[3][2], bl[3][2];
                ldsm4(ah[0], aAh + k * 2);
                ldsm4(ah[1], aAh + k * 2 + 16 * S128);
                ldsm4(al[0], aAl + k * 2);
                ldsm4(al[1], aAl + k * 2 + 16 * S128);
                ldsm4t(&bh[0][0], sb + O_WBH + aB4 + k * SW);   // nt0,nt1
                ldsm2t(bh[2],     sb + O_WBH + aB2 + k * SW);   // nt2
                ldsm4t(&bl[0][0], sb + O_WBL + aB4 + k * SW);
                ldsm2t(bl[2],     sb + O_WBL + aB2 + k * SW);
                #pragma unroll
                for (int mt = 0; mt < 2; ++mt)
                    #pragma unroll
                    for (int nt = 0; nt < 3; ++nt) {
                        mma16816(acc[mt * 3 + nt], ah[mt], bh[nt]);
                        mma16816(acc[mt * 3 + nt], ah[mt], bl[nt]);
                        mma16816(acc[mt * 3 + nt], al[mt], bh[nt]);
                    }
            }
            // epilogue: Q (scaled bf16), K (bf16), V (fp16) — u32-packed
            #pragma unroll
            for (int mt = 0; mt < 2; ++mt)
                #pragma unroll
                for (int nt = 0; nt < 3; ++nt) {
                    int nb = n0 + nt * 8;
                    #pragma unroll
                    for (int hf = 0; hf < 2; ++hf) {
                        int t = m0 + mt * 16 + hf * 8 + g;
                        float v0 = acc[mt * 3 + nt][hf * 2 + 0];
                        float v1 = acc[mt * 3 + nt][hf * 2 + 1];
                        int n = nb + qj * 2;
                        if (nb < 32) {
                            *reinterpret_cast<uint32_t*>(sm + O_QT + t * S32 + n * 2)
                                = packbf(v0 * SCALE, v1 * SCALE);
                        } else if (nb < 64) {
                            *reinterpret_cast<uint32_t*>(sm + O_KT + t * S32 + (n - 32) * 2)
                                = packbf(v0, v1);
                        } else {
                            *reinterpret_cast<uint32_t*>(sm + O_VF + t * S32 + (n - 64) * 2)
                                = packh(v0, v1);
                        }
                    }
                }
        }
        __syncthreads();

        // ---- G2: S = Q K^T (M128 N128 K32) + causal softmax -> P fp16 ----
        {
            const int m0 = wr * 32, n0 = wc * 32;
            const bool dead = (wc > wr);
            float* red = reinterpret_cast<float*>(sm + O_RED);
            float sc[8][4];
            float mloc[4], fac[4];

            if (!dead) {
                #pragma unroll
                for (int f = 0; f < 8; ++f)
                    #pragma unroll
                    for (int r = 0; r < 4; ++r) sc[f][r] = 0.f;

                const uint32_t aA  = sb + O_QT + (m0 + (lane & 15)) * S32 + ((lane >> 4) * 8) * 2;
                const uint32_t aB4 = sb + O_KT
                    + (n0 + (lane >> 4) * 8 + (lane & 7)) * S32 + (((lane >> 3) & 1) * 8) * 2;
                #pragma unroll
                for (int k = 0; k < 32; k += 16) {
                    uint32_t qa[2][4], kb[4][2];
                    ldsm4(qa[0], aA + k * 2);
                    ldsm4(qa[1], aA + k * 2 + 16 * S32);
                    ldsm4(&kb[0][0], aB4 + k * 2);
                    ldsm4(&kb[2][0], aB4 + 16 * S32 + k * 2);
                    #pragma unroll
                    for (int mt = 0; mt < 2; ++mt)
                        #pragma unroll
                        for (int nt = 0; nt < 4; ++nt)
                            mma16816(sc[mt * 4 + nt], qa[mt], kb[nt]);
                }

                #pragma unroll
                for (int ri = 0; ri < 4; ++ri) {
                    int mt = ri >> 1, hf = ri & 1;
                    int t = m0 + mt * 16 + hf * 8 + g;
                    float mx = -3.0e38f;
                    #pragma unroll
                    for (int nt = 0; nt < 4; ++nt)
                        #pragma unroll
                        for (int j = 0; j < 2; ++j) {
                            int s = n0 + nt * 8 + qj * 2 + j;
                            float v = sc[mt * 4 + nt][hf * 2 + j];
                            if (s <= t) mx = fmaxf(mx, v);
                            else sc[mt * 4 + nt][hf * 2 + j] = -3.0e38f;
                        }
                    mx = fmaxf(mx, __shfl_xor_sync(0xffffffffu, mx, 1));
                    mx = fmaxf(mx, __shfl_xor_sync(0xffffffffu, mx, 2));
                    float s = 0.f;
                    #pragma unroll
                    for (int nt = 0; nt < 4; ++nt)
                        #pragma unroll
                        for (int j = 0; j < 2; ++j) {
                            float v = sc[mt * 4 + nt][hf * 2 + j];
                            float e = (v > -1.0e38f) ? __expf(v - mx) : 0.f;
                            sc[mt * 4 + nt][hf * 2 + j] = e;
                            s += e;
                        }
                    s += __shfl_xor_sync(0xffffffffu, s, 1);
                    s += __shfl_xor_sync(0xffffffffu, s, 2);
                    mloc[ri] = mx;
                    if (qj == 0) {
                        red[(wc * 2 + 0) * 128 + t] = mx;
                        red[(wc * 2 + 1) * 128 + t] = s;
                    }
                }
            } else if (qj == 0) {
                #pragma unroll
                for (int ri = 0; ri < 4; ++ri) {
                    int mt = ri >> 1, hf = ri & 1;
                    int t = m0 + mt * 16 + hf * 8 + g;
                    red[(wc * 2 + 0) * 128 + t] = -3.0e38f;
                    red[(wc * 2 + 1) * 128 + t] = 0.f;
                }
            }
            __syncthreads();

            if (!dead) {
                #pragma unroll
                for (int ri = 0; ri < 4; ++ri) {
                    int mt = ri >> 1, hf = ri & 1;
                    int t = m0 + mt * 16 + hf * 8 + g;
                    float m = -3.0e38f;
                    #pragma unroll
                    for (int w4 = 0; w4 < 4; ++w4) m = fmaxf(m, red[(w4 * 2) * 128 + t]);
                    float sum = 0.f;
                    #pragma unroll
                    for (int w4 = 0; w4 < 4; ++w4)
                        sum += red[(w4 * 2 + 1) * 128 + t] * __expf(red[(w4 * 2) * 128 + t] - m);
                    fac[ri] = __expf(mloc[ri] - m) / sum;
                }
                // store P fp16 (dead tiles never read by bounded G3)
                #pragma unroll
                for (int ri = 0; ri < 4; ++ri) {
                    int mt = ri >> 1, hf = ri & 1;
                    int t = m0 + mt * 16 + hf * 8 + g;
                    #pragma unroll
                    for (int nt = 0; nt < 4; ++nt) {
                        int s0 = n0 + nt * 8 + qj * 2;
                        *reinterpret_cast<uint32_t*>(sm + O_PF + t * S128 + s0 * 2)
                            = packh(sc[mt * 4 + nt][hf * 2 + 0] * fac[ri],
                                    sc[mt * 4 + nt][hf * 2 + 1] * fac[ri]);
                    }
                }
            }
        }
        __syncthreads();

        // ---- G3: O = P V (fp16 single pass, causal-bounded K) ----
        {
            const int m0 = wr * 32, n0 = wc * 8;
            float oc[2][4];
            #pragma unroll
            for (int f = 0; f < 2; ++f)
                #pragma unroll
                for (int r = 0; r < 4; ++r) oc[f][r] = 0.f;

            const uint32_t aPf = sb + O_PF + (m0 + (lane & 15)) * S128 + ((lane >> 4) * 8) * 2;
            const uint32_t aVt = (uint32_t)lane * S32 + n0 * 2;   // 32 rows s per x4t
            const int kend = (wr + 1) * 32;                       // P[t][s]=0 for s>t
            for (int k32 = 0; k32 < kend; k32 += 32) {
                uint32_t vf[4];
                ldsm4t(vf, sb + O_VF + aVt + k32 * S32);
                #pragma unroll
                for (int kc = 0; kc < 2; ++kc) {
                    int k = k32 + kc * 16;
                    uint32_t pf[2][4];
                    ldsm4(pf[0], aPf + k * 2);
                    ldsm4(pf[1], aPf + k * 2 + 16 * S128);
                    #pragma unroll
                    for (int mt = 0; mt < 2; ++mt)
                        mma16816h(oc[mt], pf[mt], vf + 2 * kc);
                }
            }
            #pragma unroll
            for (int mt = 0; mt < 2; ++mt)
                #pragma unroll
                for (int hf = 0; hf < 2; ++hf) {
                    int t = m0 + mt * 16 + hf * 8 + g;
                    int d0 = n0 + qj * 2;
                    *reinterpret_cast<uint32_t*>(sm + O_OF + t * S32 + d0 * 2)
                        = packh(oc[mt][hf * 2 + 0], oc[mt][hf * 2 + 1]);
                }
        }
        __syncthreads();

        // ---- G4: OUT += O Wp^T (fp16 single pass, reg-persistent) ----
        {
            const int m0 = wr * 32, n0 = wc * 32;
            const uint32_t aOf = sb + O_OF + (m0 + (lane & 15)) * S32 + ((lane >> 4) * 8) * 2;
            const uint32_t aW4 = (uint32_t)(n0 + (lane >> 4) * 8 + (lane & 7)) * S32
                                 + (((lane >> 3) & 1) * 8) * 2;
            #pragma unroll
            for (int k = 0; k < 32; k += 16) {
                uint32_t of[2][4], wf[4][2];
                ldsm4(of[0], aOf + k * 2);
                ldsm4(of[1], aOf + k * 2 + 16 * S32);
                ldsm4(&wf[0][0], sb + O_WPF + aW4 + k * 2);
                ldsm4(&wf[2][0], sb + O_WPF + aW4 + 16 * S32 + k * 2);
                #pragma unroll
                for (int mt = 0; mt < 2; ++mt)
                    #pragma unroll
                    for (int nt = 0; nt < 4; ++nt)
                        mma16816h(oacc[mt * 4 + nt], of[mt], wf[nt]);
            }
        }
        __syncthreads();   // next head's staging overwrites W/Wp regions
    }

    // ---- final store: out = oacc + bp ----
    {
        const int m0 = wr * 32, n0 = wc * 32;
        #pragma unroll
        for (int mt = 0; mt < 2; ++mt)
            #pragma unroll
            for (int nt = 0; nt < 4; ++nt) {
                int c = n0 + nt * 8 + qj * 2;
                float2 bv = *reinterpret_cast<const float2*>(bp + c);
                #pragma unroll
                for (int hf = 0; hf < 2; ++hf) {
                    int t = m0 + mt * 16 + hf * 8 + g;
                    float2 v;
                    v.x = oacc[mt * 4 + nt][hf * 2 + 0] + bv.x;
                    v.y = oacc[mt * 4 + nt][hf * 2 + 1] + bv.y;
                    *reinterpret_cast<float2*>(out + ((size_t)b * 128 + t) * 128 + c) = v;
                }
            }
    }
}

extern "C" void kernel_launch(void* const* d_in, const int* in_sizes, int n_in,
                              void* d_out, int out_size)
{
    (void)in_sizes; (void)n_in; (void)out_size;
    const float* x  = (const float*)d_in[0];
    const float* Wq = (const float*)d_in[1];
    const float* Wk = (const float*)d_in[2];
    const float* Wv = (const float*)d_in[3];
    const float* Wp = (const float*)d_in[4];
    const float* bp = (const float*)d_in[5];
    float* out = (float*)d_out;

    cudaFuncSetAttribute(mha_mma_kernel,
                         cudaFuncAttributeMaxDynamicSharedMemorySize, SMEM_BYTES);
    mha_mma_kernel<<<NB, 512, SMEM_BYTES>>>(x, Wq, Wk, Wv, Wp, bp, out);
}